// round 6
// baseline (speedup 1.0000x reference)
#include <cuda_runtime.h>
#include <cstdint>

#define B_TOT 32768
#define F_TOT 256
#define H1 16
#define H2 8

#define BB 256   // batch elements per block
#define FT 8     // features per block (one warp per feature)
#define NP 4     // f32x2 pairs per thread (8 batch elements)
#define NFG (F_TOT / FT)   // 32 feature groups

#define LOG2E 1.4426950408889634f
#define LN2   0.6931471805599453f

typedef unsigned long long u64;

// scratch: per-(feature-group, batch) partial dot products  (4 MB)
__device__ float g_partial[NFG * B_TOT];

__device__ __forceinline__ u64 f2pack(float lo, float hi) {
    u64 r; asm("mov.b64 %0, {%1, %2};" : "=l"(r) : "f"(lo), "f"(hi)); return r;
}
__device__ __forceinline__ void f2unpack(u64 p, float& lo, float& hi) {
    asm("mov.b64 {%0, %1}, %2;" : "=f"(lo), "=f"(hi) : "l"(p));
}
__device__ __forceinline__ u64 fma2(u64 a, u64 b, u64 c) {
    u64 r; asm("fma.rn.f32x2 %0, %1, %2, %3;" : "=l"(r) : "l"(a), "l"(b), "l"(c)); return r;
}
__device__ __forceinline__ u64 mul2(u64 a, u64 b) {
    u64 r; asm("mul.rn.f32x2 %0, %1, %2;" : "=l"(r) : "l"(a), "l"(b)); return r;
}
__device__ __forceinline__ u64 add2(u64 a, u64 b) {
    u64 r; asm("add.rn.f32x2 %0, %1, %2;" : "=l"(r) : "l"(a), "l"(b)); return r;
}
__device__ __forceinline__ float ex2f(float x) {
    float r; asm("ex2.approx.ftz.f32 %0, %1;" : "=f"(r) : "f"(x)); return r;
}

// ELU on a packed pre-activation ALREADY SCALED by log2(e):
//   input s = log2e * v  (so exp(v) = ex2(s), and sign(s) == sign(v))
//   elu(v) = v > 0 ? v : exp(v) - 1,  with v = s * ln2
// Issues: 2 MUFU + 1 add2 + 1 mul2 + 2 FSETP + 2 FSEL = 8/pair
__device__ __forceinline__ u64 elu2s(u64 s2, u64 NEG1, u64 LN2D) {
    float s0, s1; f2unpack(s2, s0, s1);
    float e0 = ex2f(s0);
    float e1 = ex2f(s1);
    u64 em1 = add2(f2pack(e0, e1), NEG1);
    u64 v2  = mul2(s2, LN2D);
    float va, vb; f2unpack(v2, va, vb);
    float ea, eb; f2unpack(em1, ea, eb);
    float r0 = s0 > 0.0f ? va : ea;
    float r1 = s1 > 0.0f ? vb : eb;
    return f2pack(r0, r1);
}

__global__ __launch_bounds__(256) void mlp_z_kernel(
    const float* __restrict__ x,
    const float* __restrict__ W1, const float* __restrict__ b1,
    const float* __restrict__ W2, const float* __restrict__ b2,
    const float* __restrict__ W3, const float* __restrict__ b3,
    const float* __restrict__ theta,
    float* __restrict__ Z)
{
    __shared__ float s_x[FT][BB];     // 8 KB
    __shared__ float s_z[FT][BB];     // 8 KB
    // Duplicated {w, w} pairs (LDS.64 broadcast). W1,b1,W2,b2 pre-scaled by log2e.
    __shared__ u64 sW1d[FT * H1];
    __shared__ u64 sb1d[FT * H1];
    __shared__ u64 sW2d[FT * H1 * H2];
    __shared__ u64 sb2d[FT * H2];
    __shared__ u64 sW3d[FT * H2];
    __shared__ float sb3[FT];
    __shared__ float s_sw[FT];        // softplus(theta) for this feature group

    const int t  = threadIdx.x;
    const int b0 = blockIdx.x * BB;
    const int f0 = blockIdx.y * FT;

    // ---- params -> smem (duplicated into f32x2; layer-1/2 scaled by log2e) ----
    if (t < FT * H1) {
        float w = W1[f0 * H1 + t] * LOG2E;  sW1d[t] = f2pack(w, w);
        float b = b1[f0 * H1 + t] * LOG2E;  sb1d[t] = f2pack(b, b);
    }
    #pragma unroll
    for (int i = t; i < FT * H1 * H2; i += 256) {
        float w = W2[f0 * H1 * H2 + i] * LOG2E;  sW2d[i] = f2pack(w, w);
    }
    if (t < FT * H2) {
        float b = b2[f0 * H2 + t] * LOG2E;  sb2d[t] = f2pack(b, b);
        float w = W3[f0 * H2 + t];          sW3d[t] = f2pack(w, w);
    }
    if (t < FT) {
        sb3[t] = b3[f0 + t];
        s_sw[t] = log1pf(__expf(theta[f0 + t]));
    }

    // ---- x tile [BB x FT] coalesced float4 -> f-major smem ----
    #pragma unroll
    for (int i = t; i < BB * 2; i += 256) {
        const int bl = i >> 1;
        const int fq = (i & 1) * 4;
        const float4 v = *reinterpret_cast<const float4*>(
            x + (size_t)(b0 + bl) * F_TOT + f0 + fq);
        s_x[fq + 0][bl] = v.x;
        s_x[fq + 1][bl] = v.y;
        s_x[fq + 2][bl] = v.z;
        s_x[fq + 3][bl] = v.w;
    }
    __syncthreads();

    const int w = t >> 5;
    const int l = t & 31;

    const u64 NEG1 = f2pack(-1.0f, -1.0f);
    const u64 LN2D = f2pack(LN2, LN2);

    u64 xp[NP];
    #pragma unroll
    for (int u = 0; u < NP; u++)
        xp[u] = f2pack(s_x[w][l + 64 * u], s_x[w][l + 64 * u + 32]);

    // acc accumulates log2e * (h1.W2 + b2)  (scaled weights)
    u64 acc[NP][H2];
    #pragma unroll
    for (int k = 0; k < H2; k++) {
        const u64 bv = sb2d[w * H2 + k];
        #pragma unroll
        for (int u = 0; u < NP; u++) acc[u][k] = bv;
    }

    #pragma unroll
    for (int h = 0; h < H1; h++) {
        const u64 w1 = sW1d[w * H1 + h];   // scaled
        const u64 bb = sb1d[w * H1 + h];   // scaled
        u64 h1p[NP];
        #pragma unroll
        for (int u = 0; u < NP; u++)
            h1p[u] = elu2s(fma2(xp[u], w1, bb), NEG1, LN2D);  // s = log2e*v
        #pragma unroll
        for (int k = 0; k < H2; k++) {
            const u64 w2 = sW2d[(w * H1 + h) * H2 + k];   // scaled
            #pragma unroll
            for (int u = 0; u < NP; u++)
                acc[u][k] = fma2(h1p[u], w2, acc[u][k]);
        }
    }

    // epilogue: Z = elu(acc/log2e) . W3 + b3   (acc is pre-scaled input to elu2s)
    {
        const float b3v = sb3[w];
        #pragma unroll
        for (int u = 0; u < NP; u++) {
            u64 z = f2pack(b3v, b3v);
            #pragma unroll
            for (int k = 0; k < H2; k++)
                z = fma2(elu2s(acc[u][k], NEG1, LN2D), sW3d[w * H2 + k], z);
            float z0, z1; f2unpack(z, z0, z1);
            s_z[w][l + 64 * u]      = z0;
            s_z[w][l + 64 * u + 32] = z1;
        }
    }
    __syncthreads();

    // ---- Z tile -> gmem coalesced float4 ----
    #pragma unroll
    for (int i = t; i < BB * 2; i += 256) {
        const int bl = i >> 1;
        const int fq = (i & 1) * 4;
        float4 v;
        v.x = s_z[fq + 0][bl];
        v.y = s_z[fq + 1][bl];
        v.z = s_z[fq + 2][bl];
        v.w = s_z[fq + 3][bl];
        *reinterpret_cast<float4*>(Z + (size_t)(b0 + bl) * F_TOT + f0 + fq) = v;
    }

    // ---- fused partial reduction: ps[b] = sum_f s_z[f][b] * softplus(theta[f]) ----
    {
        float ps = 0.0f;
        #pragma unroll
        for (int f = 0; f < FT; f++)
            ps = fmaf(s_z[f][t], s_sw[f], ps);
        g_partial[blockIdx.y * B_TOT + b0 + t] = ps;
    }
}

// y[b] = bias + sum_g partial[g][b]; first 2 blocks write weights = softplus(theta)
// 256 blocks x 128 threads -> all SMs active.
__global__ __launch_bounds__(128) void reduce2_kernel(
    const float* __restrict__ theta,
    const float* __restrict__ bias,
    float* __restrict__ y,
    float* __restrict__ wout)
{
    const int t = threadIdx.x;
    if (blockIdx.x < 2) {
        const int f = blockIdx.x * 128 + t;
        wout[f] = log1pf(__expf(theta[f]));
    }

    const int b = blockIdx.x * 128 + t;
    float a = bias[0];
    #pragma unroll
    for (int g = 0; g < NFG; g++)
        a += g_partial[g * B_TOT + b];
    y[b] = a;
}

extern "C" void kernel_launch(void* const* d_in, const int* in_sizes, int n_in,
                              void* d_out, int out_size)
{
    const float* x     = (const float*)d_in[0];
    const float* W1    = (const float*)d_in[1];
    const float* b1    = (const float*)d_in[2];
    const float* W2    = (const float*)d_in[3];
    const float* b2    = (const float*)d_in[4];
    const float* W3    = (const float*)d_in[5];
    const float* b3    = (const float*)d_in[6];
    const float* theta = (const float*)d_in[7];
    const float* bias  = (const float*)d_in[8];

    float* out = (float*)d_out;
    float* y    = out;                 // [B]
    float* wout = out + B_TOT;         // [F]
    float* Z    = out + B_TOT + F_TOT; // [B, F]

    dim3 grid(B_TOT / BB, F_TOT / FT);   // (128, 32)
    mlp_z_kernel<<<grid, 256>>>(x, W1, b1, W2, b2, W3, b3, theta, Z);

    reduce2_kernel<<<B_TOT / 128, 128>>>(theta, bias, y, wout);
}

// round 7
// speedup vs baseline: 1.2628x; 1.2628x over previous
#include <cuda_runtime.h>
#include <cstdint>

#define B_TOT 32768
#define F_TOT 256
#define H1 16
#define H2 8

#define BB 256   // batch elements per block
#define FT 8     // features per block (one warp per feature)
#define NP 4     // f32x2 pairs per thread (8 batch elements)
#define NFG (F_TOT / FT)   // 32 feature groups

typedef unsigned long long u64;

// scratch: per-(feature-group, batch) partial dot products  (4 MB)
__device__ float g_partial[NFG * B_TOT];

__device__ __forceinline__ u64 f2pack(float lo, float hi) {
    u64 r; asm("mov.b64 %0, {%1, %2};" : "=l"(r) : "f"(lo), "f"(hi)); return r;
}
__device__ __forceinline__ void f2unpack(u64 p, float& lo, float& hi) {
    asm("mov.b64 {%0, %1}, %2;" : "=f"(lo), "=f"(hi) : "l"(p));
}
__device__ __forceinline__ u64 fma2(u64 a, u64 b, u64 c) {
    u64 r; asm("fma.rn.f32x2 %0, %1, %2, %3;" : "=l"(r) : "l"(a), "l"(b), "l"(c)); return r;
}
__device__ __forceinline__ float ex2f(float x) {
    float r; asm("ex2.approx.ftz.f32 %0, %1;" : "=f"(r) : "f"(x)); return r;
}

// Packed ELU, proven R3/R5 version — do not modify:
// unpack + 2x FMUL-imm + 2x MUFU + 2x FADD + 2x FSETP/FSEL + pack
__device__ __forceinline__ u64 elu2(u64 v2) {
    float v0, v1; f2unpack(v2, v0, v1);
    float e0 = ex2f(v0 * 1.4426950408889634f);
    float e1 = ex2f(v1 * 1.4426950408889634f);
    float r0 = v0 > 0.0f ? v0 : e0 - 1.0f;
    float r1 = v1 > 0.0f ? v1 : e1 - 1.0f;
    return f2pack(r0, r1);
}

__global__ __launch_bounds__(256) void mlp_z_kernel(
    const float* __restrict__ x,
    const float* __restrict__ W1, const float* __restrict__ b1,
    const float* __restrict__ W2, const float* __restrict__ b2,
    const float* __restrict__ W3, const float* __restrict__ b3,
    const float* __restrict__ theta,
    float* __restrict__ Z)
{
    __shared__ float s_x[FT][BB];     // 8 KB
    __shared__ float s_z[FT][BB];     // 8 KB
    // Duplicated {w, w} pairs: packed operand in one broadcast LDS.64
    __shared__ u64 sW1d[FT * H1];
    __shared__ u64 sb1d[FT * H1];
    __shared__ u64 sW2d[FT * H1 * H2];
    __shared__ u64 sb2d[FT * H2];
    __shared__ u64 sW3d[FT * H2];
    __shared__ float sb3[FT];
    __shared__ float s_sw[FT];        // softplus(theta) for this feature group

    const int t  = threadIdx.x;
    const int b0 = blockIdx.x * BB;
    const int f0 = blockIdx.y * FT;

    // ---- params -> smem (duplicated into f32x2) ----
    if (t < FT * H1) {
        float w = W1[f0 * H1 + t];  sW1d[t] = f2pack(w, w);
        float b = b1[f0 * H1 + t];  sb1d[t] = f2pack(b, b);
    }
    #pragma unroll
    for (int i = t; i < FT * H1 * H2; i += 256) {
        float w = W2[f0 * H1 * H2 + i];  sW2d[i] = f2pack(w, w);
    }
    if (t < FT * H2) {
        float b = b2[f0 * H2 + t];  sb2d[t] = f2pack(b, b);
        float w = W3[f0 * H2 + t];  sW3d[t] = f2pack(w, w);
    }
    if (t < FT) {
        sb3[t] = b3[f0 + t];
        s_sw[t] = log1pf(__expf(theta[f0 + t]));
    }

    // ---- x tile [BB x FT] coalesced float4 -> f-major smem ----
    #pragma unroll
    for (int i = t; i < BB * 2; i += 256) {
        const int bl = i >> 1;
        const int fq = (i & 1) * 4;
        const float4 v = *reinterpret_cast<const float4*>(
            x + (size_t)(b0 + bl) * F_TOT + f0 + fq);
        s_x[fq + 0][bl] = v.x;
        s_x[fq + 1][bl] = v.y;
        s_x[fq + 2][bl] = v.z;
        s_x[fq + 3][bl] = v.w;
    }
    __syncthreads();

    const int w = t >> 5;
    const int l = t & 31;

    u64 xp[NP];
    #pragma unroll
    for (int u = 0; u < NP; u++)
        xp[u] = f2pack(s_x[w][l + 64 * u], s_x[w][l + 64 * u + 32]);

    u64 acc[NP][H2];
    #pragma unroll
    for (int k = 0; k < H2; k++) {
        const u64 bv = sb2d[w * H2 + k];
        #pragma unroll
        for (int u = 0; u < NP; u++) acc[u][k] = bv;
    }

    #pragma unroll
    for (int h = 0; h < H1; h++) {
        const u64 w1 = sW1d[w * H1 + h];
        const u64 bb = sb1d[w * H1 + h];
        u64 h1p[NP];
        #pragma unroll
        for (int u = 0; u < NP; u++)
            h1p[u] = elu2(fma2(xp[u], w1, bb));
        #pragma unroll
        for (int k = 0; k < H2; k++) {
            const u64 w2 = sW2d[(w * H1 + h) * H2 + k];
            #pragma unroll
            for (int u = 0; u < NP; u++)
                acc[u][k] = fma2(h1p[u], w2, acc[u][k]);
        }
    }

    // epilogue: Z = elu(acc) . W3 + b3
    {
        const float b3v = sb3[w];
        #pragma unroll
        for (int u = 0; u < NP; u++) {
            u64 z = f2pack(b3v, b3v);
            #pragma unroll
            for (int k = 0; k < H2; k++)
                z = fma2(elu2(acc[u][k]), sW3d[w * H2 + k], z);
            float z0, z1; f2unpack(z, z0, z1);
            s_z[w][l + 64 * u]      = z0;
            s_z[w][l + 64 * u + 32] = z1;
        }
    }
    __syncthreads();

    // ---- Z tile -> gmem coalesced float4 ----
    #pragma unroll
    for (int i = t; i < BB * 2; i += 256) {
        const int bl = i >> 1;
        const int fq = (i & 1) * 4;
        float4 v;
        v.x = s_z[fq + 0][bl];
        v.y = s_z[fq + 1][bl];
        v.z = s_z[fq + 2][bl];
        v.w = s_z[fq + 3][bl];
        *reinterpret_cast<float4*>(Z + (size_t)(b0 + bl) * F_TOT + f0 + fq) = v;
    }

    // ---- fused partial reduction: ps[b] = sum_f s_z[f][b] * softplus(theta[f]) ----
    {
        float ps = 0.0f;
        #pragma unroll
        for (int f = 0; f < FT; f++)
            ps = fmaf(s_z[f][t], s_sw[f], ps);
        g_partial[blockIdx.y * B_TOT + b0 + t] = ps;
    }
}

// Final reduction with 4 threads per batch element (131K threads chip-wide).
// Thread layout per 256-thread block: 64 batch elems, quarter q = t>>6 sums
// feature-groups [q*8, q*8+8), then smem combine.
// First 4 blocks also write weights = softplus(theta) (64 features each).
__global__ __launch_bounds__(256) void reduce2_kernel(
    const float* __restrict__ theta,
    const float* __restrict__ bias,
    float* __restrict__ y,
    float* __restrict__ wout)
{
    __shared__ float s_p[256];
    const int t  = threadIdx.x;
    const int bl = t & 63;        // batch element within block
    const int q  = t >> 6;        // quarter: which 8 feature-groups

    if (blockIdx.x < 4) {
        const int f = blockIdx.x * 64 + bl;
        if (q == 0) wout[f] = log1pf(__expf(theta[f]));
    }

    const int b = blockIdx.x * 64 + bl;
    float a = 0.0f;
    #pragma unroll
    for (int g = 0; g < NFG / 4; g++)
        a += g_partial[(q * (NFG / 4) + g) * B_TOT + b];
    s_p[t] = a;
    __syncthreads();

    if (t < 64) {
        float r = bias[0] + s_p[t] + s_p[t + 64] + s_p[t + 128] + s_p[t + 192];
        y[b] = r;
    }
}

extern "C" void kernel_launch(void* const* d_in, const int* in_sizes, int n_in,
                              void* d_out, int out_size)
{
    const float* x     = (const float*)d_in[0];
    const float* W1    = (const float*)d_in[1];
    const float* b1    = (const float*)d_in[2];
    const float* W2    = (const float*)d_in[3];
    const float* b2    = (const float*)d_in[4];
    const float* W3    = (const float*)d_in[5];
    const float* b3    = (const float*)d_in[6];
    const float* theta = (const float*)d_in[7];
    const float* bias  = (const float*)d_in[8];

    float* out = (float*)d_out;
    float* y    = out;                 // [B]
    float* wout = out + B_TOT;         // [F]
    float* Z    = out + B_TOT + F_TOT; // [B, F]

    dim3 grid(B_TOT / BB, F_TOT / FT);   // (128, 32)
    mlp_z_kernel<<<grid, 256>>>(x, W1, b1, W2, b2, W3, b3, theta, Z);

    reduce2_kernel<<<B_TOT / 64, 256>>>(theta, bias, y, wout);
}